// round 1
// baseline (speedup 1.0000x reference)
#include <cuda_runtime.h>
#include <math.h>

// Problem shape (fixed by reference setup_inputs)
#define B  32
#define HH 112
#define WW 112
#define HW (HH*WW)        // 12544
#define C  256
#define CR 16             // C / r

// Scratch (no cudaMalloc allowed)
__device__ float g_sums[B * C];
__device__ float g_se[B * C];

// ---------------------------------------------------------------------------
// Kernel 0: zero the partial-sum scratch
// ---------------------------------------------------------------------------
__global__ void se_zero_kernel() {
    int i = blockIdx.x * blockDim.x + threadIdx.x;
    if (i < B * C) g_sums[i] = 0.0f;
}

// ---------------------------------------------------------------------------
// Kernel 1: partial spatial sums. grid = B * SPLITS blocks, 256 threads.
// Each block handles one batch b and a contiguous chunk of HW positions.
// Thread layout: qid = tid % 64 -> channel quad (4 consecutive channels,
// float4 load), prow = tid / 64 -> position sub-lane (4 positions in flight).
// ---------------------------------------------------------------------------
#define SPLITS 16
#define CHUNK  (HW / SPLITS)   // 784, divisible by 4

__global__ __launch_bounds__(256) void se_pool_kernel(const float* __restrict__ in) {
    int blk = blockIdx.x;
    int b = blk / SPLITS;
    int s = blk % SPLITS;
    int tid = threadIdx.x;
    int qid  = tid & 63;   // channel quad index: channels [4*qid, 4*qid+3]
    int prow = tid >> 6;   // 0..3

    const float4* __restrict__ in4 =
        reinterpret_cast<const float4*>(in + (size_t)b * HW * C);

    int pos_begin = s * CHUNK;
    float4 acc = make_float4(0.f, 0.f, 0.f, 0.f);

    // each position's C=256 floats = 64 float4; quad qid at offset pos*64+qid
    #pragma unroll 4
    for (int p = prow; p < CHUNK; p += 4) {
        float4 v = in4[(size_t)(pos_begin + p) * 64 + qid];
        acc.x += v.x; acc.y += v.y; acc.z += v.z; acc.w += v.w;
    }

    float* dst = &g_sums[b * C + 4 * qid];
    atomicAdd(dst + 0, acc.x);
    atomicAdd(dst + 1, acc.y);
    atomicAdd(dst + 2, acc.z);
    atomicAdd(dst + 3, acc.w);
}

// ---------------------------------------------------------------------------
// Kernel 2: the bottleneck MLP + sigmoid. One block per batch, 256 threads.
// ---------------------------------------------------------------------------
__global__ __launch_bounds__(256) void se_mlp_kernel(
    const float* __restrict__ w1, const float* __restrict__ b1,
    const float* __restrict__ w2, const float* __restrict__ b2)
{
    __shared__ float s_mean[C];
    __shared__ float s_h[CR];

    int b = blockIdx.x;
    int tid = threadIdx.x;

    s_mean[tid] = g_sums[b * C + tid] * (1.0f / (float)HW);
    __syncthreads();

    if (tid < CR) {
        float acc = b1[tid];
        #pragma unroll 8
        for (int c = 0; c < C; c++)
            acc += s_mean[c] * w1[c * CR + tid];     // w1: [C, C/r]
        s_h[tid] = fmaxf(acc, 0.0f);                 // relu
    }
    __syncthreads();

    float acc = b2[tid];
    #pragma unroll
    for (int j = 0; j < CR; j++)
        acc += s_h[j] * w2[j * C + tid];             // w2: [C/r, C]
    g_se[b * C + tid] = 1.0f / (1.0f + __expf(-acc));  // sigmoid
}

// ---------------------------------------------------------------------------
// Kernel 3: broadcast multiply. Grid-stride over float4 elements.
// se lookup per thread is L1/L2 resident (only 32 KB of se data).
// ---------------------------------------------------------------------------
__global__ __launch_bounds__(256) void se_scale_kernel(
    const float* __restrict__ in, float* __restrict__ out)
{
    const float4* __restrict__ in4  = reinterpret_cast<const float4*>(in);
    float4*       __restrict__ out4 = reinterpret_cast<float4*>(out);
    const float4* __restrict__ se4  = reinterpret_cast<const float4*>(g_se);

    const size_t n4 = (size_t)B * HW * 64;  // total float4 count
    size_t stride = (size_t)gridDim.x * blockDim.x;

    for (size_t i = (size_t)blockIdx.x * blockDim.x + threadIdx.x; i < n4; i += stride) {
        int qid = (int)(i & 63);              // channel quad
        int b   = (int)(i / ((size_t)HW * 64));
        float4 s = __ldg(&se4[b * 64 + qid]);
        float4 v = in4[i];
        v.x *= s.x; v.y *= s.y; v.z *= s.z; v.w *= s.w;
        out4[i] = v;
    }
}

// ---------------------------------------------------------------------------
extern "C" void kernel_launch(void* const* d_in, const int* in_sizes, int n_in,
                              void* d_out, int out_size)
{
    const float* in = (const float*)d_in[0];
    const float* w1 = (const float*)d_in[1];
    const float* b1 = (const float*)d_in[2];
    const float* w2 = (const float*)d_in[3];
    const float* b2 = (const float*)d_in[4];
    float* out = (float*)d_out;

    se_zero_kernel<<<(B * C + 255) / 256, 256>>>();
    se_pool_kernel<<<B * SPLITS, 256>>>(in);
    se_mlp_kernel<<<B, 256>>>(w1, b1, w2, b2);
    se_scale_kernel<<<148 * 8, 256>>>(in, out);
}